// round 12
// baseline (speedup 1.0000x reference)
#include <cuda_runtime.h>
#include <cstdint>
#include <cstddef>

#define BB 64          // batch
#define OUTC 384       // 3 levels * 128

// ---------------- scratch (static device globals; no runtime alloc) ----------------
__device__ __align__(16) float g_pts1[BB * 1024 * 3];
__device__ __align__(16) float g_pts2[BB * 512 * 3];
__device__ float g_stats[3][12];                  // per level: x,y,z, xx,xy,xz,yy,yz,zz
__device__ float g_zsum[3][128];
__device__ float g_zsq[3][128];
__device__ unsigned g_gmax[3][BB * 128];          // monotone-encoded float max keys
__device__ unsigned g_gmin[3][BB * 128];

// monotone float<->u32 keys: a > b (float) <=> key(a) > key(b) (unsigned)
__device__ __forceinline__ unsigned f2key(float f) {
    unsigned b = __float_as_uint(f);
    return (b & 0x80000000u) ? ~b : (b | 0x80000000u);
}
__device__ __forceinline__ float key2f(unsigned k) {
    unsigned b = (k & 0x80000000u) ? (k ^ 0x80000000u) : ~k;
    return __uint_as_float(b);
}

// ---------------- one-time zero of all accumulators ----------------
__global__ void k_init() {
    int i = blockIdx.x * blockDim.x + threadIdx.x;
    int stride = gridDim.x * blockDim.x;
    for (int k = i; k < 3 * BB * 128; k += stride) {
        ((unsigned*)g_gmax)[k] = 0u;            // below all finite keys
        ((unsigned*)g_gmin)[k] = 0xFFFFFFFFu;   // above all finite keys
    }
    if (blockIdx.x == 0) {
        for (int t = threadIdx.x; t < 3 * 128; t += blockDim.x) {
            ((float*)g_zsum)[t] = 0.0f;
            ((float*)g_zsq)[t] = 0.0f;
        }
        for (int t = threadIdx.x; t < 36; t += blockDim.x)
            ((float*)g_stats)[t] = 0.0f;
    }
}

// ---------------- point moments for LEVEL 0 only (vectorized: 3xfloat4 = 4 points) ------
__global__ void k_stats1(const float4* __restrict__ p4, int nq, float* __restrict__ stats) {
    float s[9];
#pragma unroll
    for (int j = 0; j < 9; j++) s[j] = 0.0f;
    for (int i = blockIdx.x * blockDim.x + threadIdx.x; i < nq; i += gridDim.x * blockDim.x) {
        float4 a = __ldg(&p4[(size_t)i * 3 + 0]);
        float4 b = __ldg(&p4[(size_t)i * 3 + 1]);
        float4 c = __ldg(&p4[(size_t)i * 3 + 2]);
#define ACC(X, Y, Z)                                        \
        { float x = (X), y = (Y), z = (Z);                  \
          s[0] += x; s[1] += y; s[2] += z;                  \
          s[3] += x * x; s[4] += x * y; s[5] += x * z;      \
          s[6] += y * y; s[7] += y * z; s[8] += z * z; }
        ACC(a.x, a.y, a.z) ACC(a.w, b.x, b.y) ACC(b.z, b.w, c.x) ACC(c.y, c.z, c.w)
#undef ACC
    }
#pragma unroll
    for (int o = 16; o; o >>= 1) {
#pragma unroll
        for (int j = 0; j < 9; j++) s[j] += __shfl_xor_sync(0xffffffff, s[j], o);
    }
    if ((threadIdx.x & 31) == 0) {
#pragma unroll
        for (int j = 0; j < 9; j++) atomicAdd(&stats[j], s[j]);
    }
}

// ---- fused: fold BN1 analytically; h1 = relu(p*w1f+b1f); z2 = h1*w2 + b2;
//      accumulate per-channel sum/sumsq AND per-(batch,channel) max/min (no z2 store) ----
__global__ void __launch_bounds__(256) k_gemm2(const float* __restrict__ pts,
                                               const float* __restrict__ w1,
                                               const float* __restrict__ b1,
                                               const float* __restrict__ g1,
                                               const float* __restrict__ be1,
                                               const float* __restrict__ stats,
                                               float invP,
                                               const float* __restrict__ w2,
                                               const float* __restrict__ b2,
                                               float* __restrict__ zsum,
                                               float* __restrict__ zsq,
                                               unsigned* __restrict__ gmax,
                                               unsigned* __restrict__ gmin,
                                               int nbpb) {
    __shared__ float Ht[64 * 128];   // [k][p], reused as reduction buffer later
    __shared__ float w1s[192];
    __shared__ float b1s[64];
    int t = threadIdx.x;

    // folded BN1 weights (redundant per block; tiny)
    if (t < 64) {
        float mx = stats[0] * invP, my = stats[1] * invP, mz = stats[2] * invP;
        float Sxx = stats[3] * invP, Sxy = stats[4] * invP, Sxz = stats[5] * invP;
        float Syy = stats[6] * invP, Syz = stats[7] * invP, Szz = stats[8] * invP;
        float w0 = w1[t], wa = w1[64 + t], wb = w1[128 + t], b = b1[t];
        float mq = mx * w0 + my * wa + mz * wb;
        float eq2 = Sxx * w0 * w0 + Syy * wa * wa + Szz * wb * wb
                  + 2.0f * (Sxy * w0 * wa + Sxz * w0 * wb + Syz * wa * wb);
        float mean = mq + b;
        float var = eq2 - mq * mq;
        float s = g1[t] * rsqrtf(var + 1e-5f);
        float tt = be1[t] - mean * s;
        w1s[t] = w0 * s; w1s[64 + t] = wa * s; w1s[128 + t] = wb * s;
        b1s[t] = b * s + tt;
    }
    __syncthreads();

    // stage A: compute H (128 points x 64 channels), transposed into smem
    {
        int p = t >> 1, half = t & 1;
        size_t gp = (size_t)blockIdx.x * 128 + p;
        float x = pts[gp * 3 + 0], y = pts[gp * 3 + 1], z = pts[gp * 3 + 2];
        int c0 = half * 32;
#pragma unroll
        for (int cc = 0; cc < 32; cc++) {
            int c = c0 + cc;
            float h = fmaf(x, w1s[c], fmaf(y, w1s[64 + c], fmaf(z, w1s[128 + c], b1s[c])));
            Ht[c * 128 + p] = fmaxf(h, 0.0f);
        }
    }
    __syncthreads();

    // stage B: 128x128x64 GEMM, 8x8 register tiles
    int r = t >> 4, q = t & 15;
    int pr = r * 8, cq = q * 8;
    float acc[8][8];
#pragma unroll
    for (int i = 0; i < 8; i++)
#pragma unroll
        for (int j = 0; j < 8; j++) acc[i][j] = 0.0f;

#pragma unroll 4
    for (int k = 0; k < 64; k++) {
        float4 a0 = *(const float4*)&Ht[k * 128 + pr];
        float4 a1 = *(const float4*)&Ht[k * 128 + pr + 4];
        float4 w0 = __ldg((const float4*)&w2[k * 128 + cq]);
        float4 w1v = __ldg((const float4*)&w2[k * 128 + cq + 4]);
        float a[8] = {a0.x, a0.y, a0.z, a0.w, a1.x, a1.y, a1.z, a1.w};
        float w[8] = {w0.x, w0.y, w0.z, w0.w, w1v.x, w1v.y, w1v.z, w1v.w};
#pragma unroll
        for (int i = 0; i < 8; i++)
#pragma unroll
            for (int j = 0; j < 8; j++) acc[i][j] = fmaf(a[i], w[j], acc[i][j]);
    }

    // epilogue: add b2, accumulate sum / sumsq / max / min per channel
    float bv[8];
#pragma unroll
    for (int j = 0; j < 8; j++) bv[j] = __ldg(&b2[cq + j]);
    float ls[8], lq[8], lx[8], ln[8];
#pragma unroll
    for (int j = 0; j < 8; j++) {
        ls[j] = 0.0f; lq[j] = 0.0f; lx[j] = -3.4e38f; ln[j] = 3.4e38f;
    }
#pragma unroll
    for (int i = 0; i < 8; i++) {
#pragma unroll
        for (int j = 0; j < 8; j++) {
            float zr = acc[i][j] + bv[j];
            ls[j] += zr;
            lq[j] += zr * zr;
            lx[j] = fmaxf(lx[j], zr);
            ln[j] = fminf(ln[j], zr);
        }
    }

    int bb = blockIdx.x / nbpb;      // batch index for max/min aggregation
    __syncthreads();                 // done reading Ht; reuse as reduction buffer
    float* red = Ht;                 // [16][128]

    // round 1: sums
    *(float4*)&red[r * 128 + cq] = make_float4(ls[0], ls[1], ls[2], ls[3]);
    *(float4*)&red[r * 128 + cq + 4] = make_float4(ls[4], ls[5], ls[6], ls[7]);
    __syncthreads();
    if (t < 128) {
        float s = 0.0f;
#pragma unroll
        for (int rr = 0; rr < 16; rr++) s += red[rr * 128 + t];
        atomicAdd(&zsum[t], s);
    }
    __syncthreads();
    // round 2: sumsq
    *(float4*)&red[r * 128 + cq] = make_float4(lq[0], lq[1], lq[2], lq[3]);
    *(float4*)&red[r * 128 + cq + 4] = make_float4(lq[4], lq[5], lq[6], lq[7]);
    __syncthreads();
    if (t < 128) {
        float s = 0.0f;
#pragma unroll
        for (int rr = 0; rr < 16; rr++) s += red[rr * 128 + t];
        atomicAdd(&zsq[t], s);
    }
    __syncthreads();
    // round 3: max
    *(float4*)&red[r * 128 + cq] = make_float4(lx[0], lx[1], lx[2], lx[3]);
    *(float4*)&red[r * 128 + cq + 4] = make_float4(lx[4], lx[5], lx[6], lx[7]);
    __syncthreads();
    if (t < 128) {
        float s = -3.4e38f;
#pragma unroll
        for (int rr = 0; rr < 16; rr++) s = fmaxf(s, red[rr * 128 + t]);
        atomicMax(&gmax[bb * 128 + t], f2key(s));
    }
    __syncthreads();
    // round 4: min
    *(float4*)&red[r * 128 + cq] = make_float4(ln[0], ln[1], ln[2], ln[3]);
    *(float4*)&red[r * 128 + cq + 4] = make_float4(ln[4], ln[5], ln[6], ln[7]);
    __syncthreads();
    if (t < 128) {
        float s = 3.4e38f;
#pragma unroll
        for (int rr = 0; rr < 16; rr++) s = fminf(s, red[rr * 128 + t]);
        atomicMin(&gmin[bb * 128 + t], f2key(s));
    }
}

// ---------------- finalize: BN2 affine on pooled max/min + relu -> out ----------------
__global__ void k_finout(const float* __restrict__ g2, const float* __restrict__ be2,
                         const float* __restrict__ zsum, const float* __restrict__ zsq,
                         const unsigned* __restrict__ gmax, const unsigned* __restrict__ gmin,
                         float invP, float* __restrict__ out, int lv) {
    int c = threadIdx.x;   // 128
    int b = blockIdx.x;    // 64
    float mean = zsum[c] * invP;
    float var = zsq[c] * invP - mean * mean;
    float s = g2[c] * rsqrtf(var + 1e-5f);
    float t = be2[c] - mean * s;
    float Mx = key2f(gmax[b * 128 + c]);
    float Mn = key2f(gmin[b * 128 + c]);
    // maxpool commutes with monotone relu; affine handled for either sign of s
    float v = fmaxf(fmaf(Mx, s, t), fmaf(Mn, s, t));
    out[b * OUTC + lv * 128 + c] = fmaxf(v, 0.0f);
}

// ---------------- farthest point sampling + gather + next-level stats ----------------
// One block per batch. Dot-product distance: d = (pn - 2 p.c) + cn, pn=|p|^2 precomputed.
// 6 fma-pipe ops/point: 3 fma + add + fmin + fmax. Per-point index tracking moved to a
// post-loop descending equality scan (fmaxf returns an operand bitwise, so == is exact;
// descending scan -> smallest j wins, preserving jnp.argmax first-occurrence semantics).
// mv starts at 0.0f, subsuming the d>=0 clamp the u32-bits redux trick requires.
// NW=8 / PPT<=8 keeps point state at <=40 registers — the R10 spill cliff was 5 arrays
// at PPT=16 (80 regs). Reduction: R5-measured scheme (redux.max + redux.min + per-warp
// u64 slots + serial scan). Epilogue: parallel gather + next-level point moments.
template <int PPT, int NW, int NPTS>
__global__ void __launch_bounds__(NW * 32) k_fps(const float* __restrict__ pts,
                                                 float* __restrict__ outp, int m,
                                                 float* __restrict__ stats) {
    __shared__ float4 s4[NPTS];
    __shared__ int sidx[NPTS / 2];
    __shared__ unsigned long long swb[2][NW];
    const int T = NW * 32;
    const float* base = pts + (size_t)blockIdx.x * NPTS * 3;
    float* ob = outp + (size_t)blockIdx.x * m * 3;
    int t = threadIdx.x;

    float px[PPT], py[PPT], pz[PPT], pn[PPT], mind[PPT];
#pragma unroll
    for (int j = 0; j < PPT; j++) {
        int n = t + j * T;
        float x = base[n * 3 + 0], y = base[n * 3 + 1], z = base[n * 3 + 2];
        px[j] = x; py[j] = y; pz[j] = z;
        pn[j] = fmaf(z, z, fmaf(y, y, x * x));
        s4[n] = make_float4(x, y, z, 0.0f);
        mind[j] = 3.4e38f;
    }
    if (t == 0) sidx[0] = 0;
    __syncthreads();

    float4 c0 = s4[0];                       // idxs[0] = 0
    float cx = c0.x, cy = c0.y, cz = c0.z;

    for (int i = 1; i < m; i++) {
        float A = -2.0f * cx, B = -2.0f * cy, C = -2.0f * cz;
        float cn = fmaf(cz, cz, fmaf(cy, cy, cx * cx));
        float mv = 0.0f;                     // >=0 floor (distances can round to -eps)
#pragma unroll
        for (int j = 0; j < PPT; j++) {
            float d = fmaf(px[j], A, fmaf(py[j], B, fmaf(pz[j], C, pn[j]))) + cn;
            float mm = fminf(mind[j], d);
            mind[j] = mm;
            mv = fmaxf(mv, mm);
        }
        int bi = 0;
#pragma unroll
        for (int j = PPT - 1; j >= 0; j--)
            if (mind[j] == mv) bi = t + j * T;   // descending -> smallest j wins
        unsigned mvb = __float_as_uint(mv);
        unsigned wmax = __reduce_max_sync(0xffffffffu, mvb);
        unsigned cidx = (mvb == wmax) ? (unsigned)bi : 0xffffffffu;
        unsigned widx = __reduce_min_sync(0xffffffffu, cidx);
        int par = i & 1;
        if ((t & 31) == 0)
            swb[par][t >> 5] = ((unsigned long long)wmax << 32) | (unsigned)(~widx);
        __syncthreads();
        unsigned long long b = swb[par][0];
#pragma unroll
        for (int w = 1; w < NW; w++) {
            unsigned long long v = swb[par][w];
            b = v > b ? v : b;
        }
        int nxt = (int)(~(unsigned)(b & 0xffffffffu));
        float4 c = s4[nxt];
        cx = c.x; cy = c.y; cz = c.z;
        if (t == 0) sidx[i] = nxt;
    }
    __syncthreads();   // publish last sidx entries

    // epilogue: write selected points + accumulate next-level moments
    float s[9];
#pragma unroll
    for (int j = 0; j < 9; j++) s[j] = 0.0f;
    for (int i = t; i < m; i += T) {
        float4 p = s4[sidx[i]];
        ob[i * 3 + 0] = p.x; ob[i * 3 + 1] = p.y; ob[i * 3 + 2] = p.z;
        s[0] += p.x; s[1] += p.y; s[2] += p.z;
        s[3] += p.x * p.x; s[4] += p.x * p.y; s[5] += p.x * p.z;
        s[6] += p.y * p.y; s[7] += p.y * p.z; s[8] += p.z * p.z;
    }
#pragma unroll
    for (int o = 16; o; o >>= 1) {
#pragma unroll
        for (int j = 0; j < 9; j++) s[j] += __shfl_xor_sync(0xffffffff, s[j], o);
    }
    if ((t & 31) == 0) {
#pragma unroll
        for (int j = 0; j < 9; j++) atomicAdd(&stats[j], s[j]);
    }
}

// ---------------- host launcher ----------------
extern "C" void kernel_launch(void* const* d_in, const int* in_sizes, int n_in,
                              void* d_out, int out_size) {
    const float* points = (const float*)d_in[0];
    const float* w1 = (const float*)d_in[1];
    const float* b1 = (const float*)d_in[2];
    const float* g1 = (const float*)d_in[3];
    const float* be1 = (const float*)d_in[4];
    const float* w2 = (const float*)d_in[5];
    const float* b2 = (const float*)d_in[6];
    const float* g2 = (const float*)d_in[7];
    const float* be2 = (const float*)d_in[8];
    float* out = (float*)d_out;

    float *pts1, *pts2, *statsb, *zsumb, *zsqb;
    unsigned *gmaxb, *gminb;
    cudaGetSymbolAddress((void**)&pts1, g_pts1);
    cudaGetSymbolAddress((void**)&pts2, g_pts2);
    cudaGetSymbolAddress((void**)&statsb, g_stats);
    cudaGetSymbolAddress((void**)&zsumb, g_zsum);
    cudaGetSymbolAddress((void**)&zsqb, g_zsq);
    cudaGetSymbolAddress((void**)&gmaxb, g_gmax);
    cudaGetSymbolAddress((void**)&gminb, g_gmin);

    // one-time host resources (streams/events are not device memory)
    static cudaStream_t s_fps = nullptr;
    static cudaEvent_t e_root = nullptr, e_fps0 = nullptr, e_fps1 = nullptr;
    if (!s_fps) {
        cudaStreamCreateWithFlags(&s_fps, cudaStreamNonBlocking);
        cudaEventCreateWithFlags(&e_root, cudaEventDisableTiming);
        cudaEventCreateWithFlags(&e_fps0, cudaEventDisableTiming);
        cudaEventCreateWithFlags(&e_fps1, cudaEventDisableTiming);
    }

    const float* ptsl[3] = {points, pts1, pts2};

    // init FIRST (FPS epilogues atomicAdd into stats), then fork
    k_init<<<96, 256>>>();
    cudaEventRecord(e_root, 0);
    cudaStreamWaitEvent(s_fps, e_root, 0);
    k_fps<8, 8, 2048><<<BB, 256, 0, s_fps>>>(points, pts1, 1024, statsb + 1 * 12);
    cudaEventRecord(e_fps0, s_fps);
    k_fps<4, 8, 1024><<<BB, 256, 0, s_fps>>>(pts1, pts2, 512, statsb + 2 * 12);
    cudaEventRecord(e_fps1, s_fps);

    for (int lv = 0; lv < 3; lv++) {
        int N = 2048 >> lv;
        int P = BB * N;
        float invP = 1.0f / (float)P;

        if (lv == 1) cudaStreamWaitEvent(0, e_fps0, 0);   // pts1 + stats1 ready
        if (lv == 2) cudaStreamWaitEvent(0, e_fps1, 0);   // pts2 + stats2 ready

        if (lv == 0) {
            int nq = P / 4;
            k_stats1<<<128, 256>>>((const float4*)points, nq, statsb);
        }
        k_gemm2<<<P / 128, 256>>>(ptsl[lv],
                                  w1 + lv * 192, b1 + lv * 64, g1 + lv * 64, be1 + lv * 64,
                                  statsb + lv * 12, invP,
                                  w2 + lv * 8192, b2 + lv * 128,
                                  zsumb + lv * 128, zsqb + lv * 128,
                                  gmaxb + lv * BB * 128, gminb + lv * BB * 128,
                                  N / 128);
        k_finout<<<BB, 128>>>(g2 + lv * 128, be2 + lv * 128,
                              zsumb + lv * 128, zsqb + lv * 128,
                              gmaxb + lv * BB * 128, gminb + lv * BB * 128,
                              invP, out, lv);
    }
}

// round 13
// speedup vs baseline: 1.2097x; 1.2097x over previous
#include <cuda_runtime.h>
#include <cstdint>
#include <cstddef>

#define BB 64          // batch
#define OUTC 384       // 3 levels * 128

// ---------------- scratch (static device globals; no runtime alloc) ----------------
__device__ __align__(16) float g_pts1[BB * 1024 * 3];
__device__ __align__(16) float g_pts2[BB * 512 * 3];
__device__ float g_stats[3][12];                  // per level: x,y,z, xx,xy,xz,yy,yz,zz
__device__ float g_zsum[3][128];
__device__ float g_zsq[3][128];
__device__ unsigned g_gmax[3][BB * 128];          // monotone-encoded float max keys
__device__ unsigned g_gmin[3][BB * 128];

// monotone float<->u32 keys: a > b (float) <=> key(a) > key(b) (unsigned)
__device__ __forceinline__ unsigned f2key(float f) {
    unsigned b = __float_as_uint(f);
    return (b & 0x80000000u) ? ~b : (b | 0x80000000u);
}
__device__ __forceinline__ float key2f(unsigned k) {
    unsigned b = (k & 0x80000000u) ? (k ^ 0x80000000u) : ~k;
    return __uint_as_float(b);
}

// ---------------- one-time zero of all accumulators ----------------
__global__ void k_init() {
    int i = blockIdx.x * blockDim.x + threadIdx.x;
    int stride = gridDim.x * blockDim.x;
    for (int k = i; k < 3 * BB * 128; k += stride) {
        ((unsigned*)g_gmax)[k] = 0u;            // below all finite keys
        ((unsigned*)g_gmin)[k] = 0xFFFFFFFFu;   // above all finite keys
    }
    if (blockIdx.x == 0) {
        for (int t = threadIdx.x; t < 3 * 128; t += blockDim.x) {
            ((float*)g_zsum)[t] = 0.0f;
            ((float*)g_zsq)[t] = 0.0f;
        }
        for (int t = threadIdx.x; t < 36; t += blockDim.x)
            ((float*)g_stats)[t] = 0.0f;
    }
}

// ---------------- point moments for LEVEL 0 only (vectorized: 3xfloat4 = 4 points) ------
__global__ void k_stats1(const float4* __restrict__ p4, int nq, float* __restrict__ stats) {
    float s[9];
#pragma unroll
    for (int j = 0; j < 9; j++) s[j] = 0.0f;
    for (int i = blockIdx.x * blockDim.x + threadIdx.x; i < nq; i += gridDim.x * blockDim.x) {
        float4 a = __ldg(&p4[(size_t)i * 3 + 0]);
        float4 b = __ldg(&p4[(size_t)i * 3 + 1]);
        float4 c = __ldg(&p4[(size_t)i * 3 + 2]);
#define ACC(X, Y, Z)                                        \
        { float x = (X), y = (Y), z = (Z);                  \
          s[0] += x; s[1] += y; s[2] += z;                  \
          s[3] += x * x; s[4] += x * y; s[5] += x * z;      \
          s[6] += y * y; s[7] += y * z; s[8] += z * z; }
        ACC(a.x, a.y, a.z) ACC(a.w, b.x, b.y) ACC(b.z, b.w, c.x) ACC(c.y, c.z, c.w)
#undef ACC
    }
#pragma unroll
    for (int o = 16; o; o >>= 1) {
#pragma unroll
        for (int j = 0; j < 9; j++) s[j] += __shfl_xor_sync(0xffffffff, s[j], o);
    }
    if ((threadIdx.x & 31) == 0) {
#pragma unroll
        for (int j = 0; j < 9; j++) atomicAdd(&stats[j], s[j]);
    }
}

// ---- fused: fold BN1 analytically; h1 = relu(p*w1f+b1f); z2 = h1*w2 + b2;
//      accumulate per-channel sum/sumsq AND per-(batch,channel) max/min (no z2 store) ----
__global__ void __launch_bounds__(256) k_gemm2(const float* __restrict__ pts,
                                               const float* __restrict__ w1,
                                               const float* __restrict__ b1,
                                               const float* __restrict__ g1,
                                               const float* __restrict__ be1,
                                               const float* __restrict__ stats,
                                               float invP,
                                               const float* __restrict__ w2,
                                               const float* __restrict__ b2,
                                               float* __restrict__ zsum,
                                               float* __restrict__ zsq,
                                               unsigned* __restrict__ gmax,
                                               unsigned* __restrict__ gmin,
                                               int nbpb) {
    __shared__ float Ht[64 * 128];   // [k][p], reused as reduction buffer later
    __shared__ float w1s[192];
    __shared__ float b1s[64];
    int t = threadIdx.x;

    // folded BN1 weights (redundant per block; tiny)
    if (t < 64) {
        float mx = stats[0] * invP, my = stats[1] * invP, mz = stats[2] * invP;
        float Sxx = stats[3] * invP, Sxy = stats[4] * invP, Sxz = stats[5] * invP;
        float Syy = stats[6] * invP, Syz = stats[7] * invP, Szz = stats[8] * invP;
        float w0 = w1[t], wa = w1[64 + t], wb = w1[128 + t], b = b1[t];
        float mq = mx * w0 + my * wa + mz * wb;
        float eq2 = Sxx * w0 * w0 + Syy * wa * wa + Szz * wb * wb
                  + 2.0f * (Sxy * w0 * wa + Sxz * w0 * wb + Syz * wa * wb);
        float mean = mq + b;
        float var = eq2 - mq * mq;
        float s = g1[t] * rsqrtf(var + 1e-5f);
        float tt = be1[t] - mean * s;
        w1s[t] = w0 * s; w1s[64 + t] = wa * s; w1s[128 + t] = wb * s;
        b1s[t] = b * s + tt;
    }
    __syncthreads();

    // stage A: compute H (128 points x 64 channels), transposed into smem
    {
        int p = t >> 1, half = t & 1;
        size_t gp = (size_t)blockIdx.x * 128 + p;
        float x = pts[gp * 3 + 0], y = pts[gp * 3 + 1], z = pts[gp * 3 + 2];
        int c0 = half * 32;
#pragma unroll
        for (int cc = 0; cc < 32; cc++) {
            int c = c0 + cc;
            float h = fmaf(x, w1s[c], fmaf(y, w1s[64 + c], fmaf(z, w1s[128 + c], b1s[c])));
            Ht[c * 128 + p] = fmaxf(h, 0.0f);
        }
    }
    __syncthreads();

    // stage B: 128x128x64 GEMM, 8x8 register tiles
    int r = t >> 4, q = t & 15;
    int pr = r * 8, cq = q * 8;
    float acc[8][8];
#pragma unroll
    for (int i = 0; i < 8; i++)
#pragma unroll
        for (int j = 0; j < 8; j++) acc[i][j] = 0.0f;

#pragma unroll 4
    for (int k = 0; k < 64; k++) {
        float4 a0 = *(const float4*)&Ht[k * 128 + pr];
        float4 a1 = *(const float4*)&Ht[k * 128 + pr + 4];
        float4 w0 = __ldg((const float4*)&w2[k * 128 + cq]);
        float4 w1v = __ldg((const float4*)&w2[k * 128 + cq + 4]);
        float a[8] = {a0.x, a0.y, a0.z, a0.w, a1.x, a1.y, a1.z, a1.w};
        float w[8] = {w0.x, w0.y, w0.z, w0.w, w1v.x, w1v.y, w1v.z, w1v.w};
#pragma unroll
        for (int i = 0; i < 8; i++)
#pragma unroll
            for (int j = 0; j < 8; j++) acc[i][j] = fmaf(a[i], w[j], acc[i][j]);
    }

    // epilogue: add b2, accumulate sum / sumsq / max / min per channel
    float bv[8];
#pragma unroll
    for (int j = 0; j < 8; j++) bv[j] = __ldg(&b2[cq + j]);
    float ls[8], lq[8], lx[8], ln[8];
#pragma unroll
    for (int j = 0; j < 8; j++) {
        ls[j] = 0.0f; lq[j] = 0.0f; lx[j] = -3.4e38f; ln[j] = 3.4e38f;
    }
#pragma unroll
    for (int i = 0; i < 8; i++) {
#pragma unroll
        for (int j = 0; j < 8; j++) {
            float zr = acc[i][j] + bv[j];
            ls[j] += zr;
            lq[j] += zr * zr;
            lx[j] = fmaxf(lx[j], zr);
            ln[j] = fminf(ln[j], zr);
        }
    }

    int bb = blockIdx.x / nbpb;      // batch index for max/min aggregation
    __syncthreads();                 // done reading Ht; reuse as reduction buffer
    float* red = Ht;                 // [16][128]

    // round 1: sums
    *(float4*)&red[r * 128 + cq] = make_float4(ls[0], ls[1], ls[2], ls[3]);
    *(float4*)&red[r * 128 + cq + 4] = make_float4(ls[4], ls[5], ls[6], ls[7]);
    __syncthreads();
    if (t < 128) {
        float s = 0.0f;
#pragma unroll
        for (int rr = 0; rr < 16; rr++) s += red[rr * 128 + t];
        atomicAdd(&zsum[t], s);
    }
    __syncthreads();
    // round 2: sumsq
    *(float4*)&red[r * 128 + cq] = make_float4(lq[0], lq[1], lq[2], lq[3]);
    *(float4*)&red[r * 128 + cq + 4] = make_float4(lq[4], lq[5], lq[6], lq[7]);
    __syncthreads();
    if (t < 128) {
        float s = 0.0f;
#pragma unroll
        for (int rr = 0; rr < 16; rr++) s += red[rr * 128 + t];
        atomicAdd(&zsq[t], s);
    }
    __syncthreads();
    // round 3: max
    *(float4*)&red[r * 128 + cq] = make_float4(lx[0], lx[1], lx[2], lx[3]);
    *(float4*)&red[r * 128 + cq + 4] = make_float4(lx[4], lx[5], lx[6], lx[7]);
    __syncthreads();
    if (t < 128) {
        float s = -3.4e38f;
#pragma unroll
        for (int rr = 0; rr < 16; rr++) s = fmaxf(s, red[rr * 128 + t]);
        atomicMax(&gmax[bb * 128 + t], f2key(s));
    }
    __syncthreads();
    // round 4: min
    *(float4*)&red[r * 128 + cq] = make_float4(ln[0], ln[1], ln[2], ln[3]);
    *(float4*)&red[r * 128 + cq + 4] = make_float4(ln[4], ln[5], ln[6], ln[7]);
    __syncthreads();
    if (t < 128) {
        float s = 3.4e38f;
#pragma unroll
        for (int rr = 0; rr < 16; rr++) s = fminf(s, red[rr * 128 + t]);
        atomicMin(&gmin[bb * 128 + t], f2key(s));
    }
}

// ---------------- finalize: BN2 affine on pooled max/min + relu -> out ----------------
__global__ void k_finout(const float* __restrict__ g2, const float* __restrict__ be2,
                         const float* __restrict__ zsum, const float* __restrict__ zsq,
                         const unsigned* __restrict__ gmax, const unsigned* __restrict__ gmin,
                         float invP, float* __restrict__ out, int lv) {
    int c = threadIdx.x;   // 128
    int b = blockIdx.x;    // 64
    float mean = zsum[c] * invP;
    float var = zsq[c] * invP - mean * mean;
    float s = g2[c] * rsqrtf(var + 1e-5f);
    float t = be2[c] - mean * s;
    float Mx = key2f(gmax[b * 128 + c]);
    float Mn = key2f(gmin[b * 128 + c]);
    // maxpool commutes with monotone relu; affine handled for either sign of s
    float v = fmaxf(fmaf(Mx, s, t), fmaf(Mn, s, t));
    out[b * OUTC + lv * 128 + c] = fmaxf(v, 0.0f);
}

// ---------------- farthest point sampling + gather + next-level stats ----------------
// EXACT R11-measured hot loop (fastest): scalar fma distance chain over 4 register arrays
// (px,py,pz,mind — a 5th PPT-array spills at PPT=16; dot-product variants measured slower
// in R10/R12), in-loop strict-> index tracking, redux.max over distance bits (>=0 so
// u32-order-preserving) + redux.min over matching indices, parity-double-buffered
// per-warp u64 slots, serial NW-slot max scan. u64 = (distbits<<32)|~idx -> max() =
// smallest-index tie-break (jnp.argmax first-occurrence semantics). Selected indices go
// to smem; epilogue writes output points in parallel AND accumulates the 9 point-moments
// for the next level's BN1 fold.
template <int PPT, int NW, int NPTS>
__global__ void __launch_bounds__(NW * 32) k_fps(const float* __restrict__ pts,
                                                 float* __restrict__ outp, int m,
                                                 float* __restrict__ stats) {
    __shared__ float4 s4[NPTS];
    __shared__ int sidx[NPTS / 2];
    __shared__ unsigned long long swb[2][NW];
    const int T = NW * 32;
    const float* base = pts + (size_t)blockIdx.x * NPTS * 3;
    float* ob = outp + (size_t)blockIdx.x * m * 3;
    int t = threadIdx.x;

    float px[PPT], py[PPT], pz[PPT], mind[PPT];
#pragma unroll
    for (int j = 0; j < PPT; j++) {
        int n = t + j * T;
        float x = base[n * 3 + 0], y = base[n * 3 + 1], z = base[n * 3 + 2];
        px[j] = x; py[j] = y; pz[j] = z;
        s4[n] = make_float4(x, y, z, 0.0f);
        mind[j] = 3.4e38f;
    }
    if (t == 0) sidx[0] = 0;
    __syncthreads();

    float4 c0 = s4[0];                       // idxs[0] = 0
    float cx = c0.x, cy = c0.y, cz = c0.z;

    for (int i = 1; i < m; i++) {
        float mv = -1.0f;
        int bi = 0;
#pragma unroll
        for (int j = 0; j < PPT; j++) {
            float dx = px[j] - cx, dy = py[j] - cy, dz = pz[j] - cz;
            float d = fmaf(dz, dz, fmaf(dy, dy, dx * dx));
            float mm = fminf(mind[j], d);
            mind[j] = mm;
            if (mm > mv) { mv = mm; bi = t + j * T; }   // strict > keeps smallest j
        }
        unsigned mvb = __float_as_uint(mv);
        unsigned wmax = __reduce_max_sync(0xffffffffu, mvb);
        unsigned cidx = (mvb == wmax) ? (unsigned)bi : 0xffffffffu;
        unsigned widx = __reduce_min_sync(0xffffffffu, cidx);
        int par = i & 1;
        if ((t & 31) == 0)
            swb[par][t >> 5] = ((unsigned long long)wmax << 32) | (unsigned)(~widx);
        __syncthreads();
        unsigned long long b = swb[par][0];
#pragma unroll
        for (int w = 1; w < NW; w++) {
            unsigned long long v = swb[par][w];
            b = v > b ? v : b;
        }
        int nxt = (int)(~(unsigned)(b & 0xffffffffu));
        float4 c = s4[nxt];
        cx = c.x; cy = c.y; cz = c.z;
        if (t == 0) sidx[i] = nxt;
    }
    __syncthreads();   // publish last sidx entries

    // epilogue: write selected points + accumulate next-level moments
    float s[9];
#pragma unroll
    for (int j = 0; j < 9; j++) s[j] = 0.0f;
    for (int i = t; i < m; i += T) {
        float4 p = s4[sidx[i]];
        ob[i * 3 + 0] = p.x; ob[i * 3 + 1] = p.y; ob[i * 3 + 2] = p.z;
        s[0] += p.x; s[1] += p.y; s[2] += p.z;
        s[3] += p.x * p.x; s[4] += p.x * p.y; s[5] += p.x * p.z;
        s[6] += p.y * p.y; s[7] += p.y * p.z; s[8] += p.z * p.z;
    }
#pragma unroll
    for (int o = 16; o; o >>= 1) {
#pragma unroll
        for (int j = 0; j < 9; j++) s[j] += __shfl_xor_sync(0xffffffff, s[j], o);
    }
    if ((t & 31) == 0) {
#pragma unroll
        for (int j = 0; j < 9; j++) atomicAdd(&stats[j], s[j]);
    }
}

// ---------------- host launcher ----------------
extern "C" void kernel_launch(void* const* d_in, const int* in_sizes, int n_in,
                              void* d_out, int out_size) {
    const float* points = (const float*)d_in[0];
    const float* w1 = (const float*)d_in[1];
    const float* b1 = (const float*)d_in[2];
    const float* g1 = (const float*)d_in[3];
    const float* be1 = (const float*)d_in[4];
    const float* w2 = (const float*)d_in[5];
    const float* b2 = (const float*)d_in[6];
    const float* g2 = (const float*)d_in[7];
    const float* be2 = (const float*)d_in[8];
    float* out = (float*)d_out;

    float *pts1, *pts2, *statsb, *zsumb, *zsqb;
    unsigned *gmaxb, *gminb;
    cudaGetSymbolAddress((void**)&pts1, g_pts1);
    cudaGetSymbolAddress((void**)&pts2, g_pts2);
    cudaGetSymbolAddress((void**)&statsb, g_stats);
    cudaGetSymbolAddress((void**)&zsumb, g_zsum);
    cudaGetSymbolAddress((void**)&zsqb, g_zsq);
    cudaGetSymbolAddress((void**)&gmaxb, g_gmax);
    cudaGetSymbolAddress((void**)&gminb, g_gmin);

    // one-time host resources (streams/events are not device memory)
    static cudaStream_t s_fps = nullptr;
    static cudaEvent_t e_root = nullptr, e_fps0 = nullptr, e_join = nullptr;
    if (!s_fps) {
        cudaStreamCreateWithFlags(&s_fps, cudaStreamNonBlocking);
        cudaEventCreateWithFlags(&e_root, cudaEventDisableTiming);
        cudaEventCreateWithFlags(&e_fps0, cudaEventDisableTiming);
        cudaEventCreateWithFlags(&e_join, cudaEventDisableTiming);
    }

    // init FIRST (FPS epilogues atomicAdd into stats; gmax/gmin zeroed), then fork
    k_init<<<96, 256>>>();
    cudaEventRecord(e_root, 0);
    cudaStreamWaitEvent(s_fps, e_root, 0);

    // ---- s_fps: FPS0 -> FPS1 -> lv2 compute chain (in-stream, no event hop) ----
    k_fps<16, 4, 2048><<<BB, 128, 0, s_fps>>>(points, pts1, 1024, statsb + 1 * 12);
    cudaEventRecord(e_fps0, s_fps);
    k_fps<8, 4, 1024><<<BB, 128, 0, s_fps>>>(pts1, pts2, 512, statsb + 2 * 12);
    {
        const int lv = 2, N = 512, P = BB * N;
        float invP = 1.0f / (float)P;
        k_gemm2<<<P / 128, 256, 0, s_fps>>>(pts2,
                                            w1 + lv * 192, b1 + lv * 64, g1 + lv * 64,
                                            be1 + lv * 64, statsb + lv * 12, invP,
                                            w2 + lv * 8192, b2 + lv * 128,
                                            zsumb + lv * 128, zsqb + lv * 128,
                                            gmaxb + lv * BB * 128, gminb + lv * BB * 128,
                                            N / 128);
        k_finout<<<BB, 128, 0, s_fps>>>(g2 + lv * 128, be2 + lv * 128,
                                        zsumb + lv * 128, zsqb + lv * 128,
                                        gmaxb + lv * BB * 128, gminb + lv * BB * 128,
                                        invP, out, lv);
    }
    cudaEventRecord(e_join, s_fps);

    // ---- stream 0: lv0 chain, then lv1 chain after pts1/stats1 ready ----
    for (int lv = 0; lv < 2; lv++) {
        int N = 2048 >> lv;
        int P = BB * N;
        float invP = 1.0f / (float)P;
        const float* p = (lv == 0) ? points : pts1;

        if (lv == 1) cudaStreamWaitEvent(0, e_fps0, 0);   // pts1 + stats1 ready
        if (lv == 0) k_stats1<<<128, 256>>>((const float4*)points, P / 4, statsb);

        k_gemm2<<<P / 128, 256>>>(p,
                                  w1 + lv * 192, b1 + lv * 64, g1 + lv * 64, be1 + lv * 64,
                                  statsb + lv * 12, invP,
                                  w2 + lv * 8192, b2 + lv * 128,
                                  zsumb + lv * 128, zsqb + lv * 128,
                                  gmaxb + lv * BB * 128, gminb + lv * BB * 128,
                                  N / 128);
        k_finout<<<BB, 128>>>(g2 + lv * 128, be2 + lv * 128,
                              zsumb + lv * 128, zsqb + lv * 128,
                              gmaxb + lv * BB * 128, gminb + lv * BB * 128,
                              invP, out, lv);
    }

    // join forked stream back into the capture-origin stream
    cudaStreamWaitEvent(0, e_join, 0);
}